// round 3
// baseline (speedup 1.0000x reference)
#include <cuda_runtime.h>
#include <cstdint>
#include <math.h>

#define MAXN 100000
#define FDIM 128
#define HID  100
#define NC   200   // 2*HID fused output columns: [z | h]

// ---------------- scratch (static device memory; no runtime allocation) ----
__device__ __align__(16) float g_deg[MAXN];
__device__ __align__(16) float g_dinv[MAXN];
__device__ __align__(16) float g_aggx[(size_t)MAXN * FDIM];   // 51.2 MB
__device__ __align__(16) float g_M[FDIM * NC];                // fused weights
__device__ __align__(16) float g_bias[NC];                    // fused biases

// explicit .global vector reduction (the generic atomicAdd(float4) overload
// lowers to a generic-space atom.v4 which traps: v4 red is .global-only PTX)
__device__ __forceinline__ void red_global_v4(float* addr, float4 v) {
    asm volatile("red.global.add.v4.f32 [%0], {%1, %2, %3, %4};"
                 :: "l"(addr), "f"(v.x), "f"(v.y), "f"(v.z), "f"(v.w)
                 : "memory");
}

// ---------------- degree = 1 (self loop) + sum_w ---------------------------
__global__ void k_deg_init(int n) {
    int i = blockIdx.x * blockDim.x + threadIdx.x;
    if (i < n) g_deg[i] = 1.0f;
}

__global__ void k_deg_acc(const int* __restrict__ ei,
                          const float* __restrict__ ew, int e) {
    int i = blockIdx.x * blockDim.x + threadIdx.x;
    if (i < e) {
        int d = ei[(size_t)e + i];
        atomicAdd(&g_deg[d], ew[i]);
    }
}

__global__ void k_dinv(int n) {
    int i = blockIdx.x * blockDim.x + threadIdx.x;
    if (i < n) {
        float dg = g_deg[i];
        g_dinv[i] = (dg > 0.0f) ? rsqrtf(dg) : 0.0f;
    }
}

// ---------------- fused weights: M = [Wcz@Wlz[:H] | Wch@Wlh[:H]] -----------
__global__ void k_fuseW(const float* __restrict__ Wcz,
                        const float* __restrict__ Wch,
                        const float* __restrict__ Wlz,
                        const float* __restrict__ Wlh) {
    int id = blockIdx.x * blockDim.x + threadIdx.x;
    if (id >= FDIM * NC) return;
    int f = id / NC, j = id % NC;
    const float* A = (j < HID) ? Wcz : Wch;
    const float* B = (j < HID) ? Wlz : Wlh;   // rows [0,HID) of [2H,H]
    int jj = (j < HID) ? j : j - HID;
    float s = 0.0f;
    #pragma unroll 4
    for (int t = 0; t < HID; t++)
        s += A[f * HID + t] * B[t * HID + jj];
    g_M[id] = s;
}

__global__ void k_fuseB(const float* __restrict__ bcz,
                        const float* __restrict__ bch,
                        const float* __restrict__ Wlz,
                        const float* __restrict__ Wlh,
                        const float* __restrict__ blz,
                        const float* __restrict__ blh) {
    int j = threadIdx.x;
    if (j >= NC) return;
    const float* bc = (j < HID) ? bcz : bch;
    const float* Wl = (j < HID) ? Wlz : Wlh;
    const float* bl = (j < HID) ? blz : blh;
    int jj = (j < HID) ? j : j - HID;
    float s = bl[jj];
    for (int t = 0; t < HID; t++)
        s += bc[t] * Wl[t * HID + jj];
    g_bias[j] = s;
}

// ---------------- self-loop init: aggx[n] = dinv[n]^2 * x[n] ---------------
__global__ void k_selfloop(const float* __restrict__ x, int n) {
    int i = blockIdx.x * blockDim.x + threadIdx.x;   // over n*32 float4s
    if (i >= n * 32) return;
    int nn = i >> 5;
    float s = g_dinv[nn];
    float s2 = s * s;
    float4 v = ((const float4*)x)[i];
    float4 r = make_float4(v.x * s2, v.y * s2, v.z * s2, v.w * s2);
    ((float4*)g_aggx)[i] = r;
}

// ---------------- edge scatter: aggx[dst] += norm * x[src] -----------------
// one warp per edge; lane handles one float4 (128 feats = 32 lanes x 4)
__global__ void k_edge(const int* __restrict__ ei,
                       const float* __restrict__ ew,
                       const float* __restrict__ x, int e) {
    int wi = (blockIdx.x * blockDim.x + threadIdx.x) >> 5;
    int lane = threadIdx.x & 31;
    if (wi >= e) return;
    int s = ei[wi];
    int d = ei[(size_t)e + wi];
    float nrm = g_dinv[s] * ew[wi] * g_dinv[d];
    float4 v = ((const float4*)(x + (size_t)s * FDIM))[lane];
    float4 r = make_float4(v.x * nrm, v.y * nrm, v.z * nrm, v.w * nrm);
    red_global_v4(g_aggx + (size_t)d * FDIM + lane * 4, r);
}

// ---------------- fused GEMM + TGCN epilogue + output GEMV -----------------
// C[n, 0:200] = aggx[n, :] @ M ; z = sigmoid(C[:,j]+b[j]), h = tanh(C[:,j+100]+b[j+100])
// out[n] = sum_j relu((1-z)*h) * Wout[j] + bout
// block: 200 threads = 8 row-threads x 25 col-threads; 64 rows/block,
// thread tile = 8 rows x (4 z-cols + 4 h-cols), K tiled by 32.
__global__ void __launch_bounds__(200) k_gemm(const float* __restrict__ Wout,
                                              const float* __restrict__ bout,
                                              float* __restrict__ out, int n) {
    __shared__ float Bs[32 * NC];       // 25.6 KB
    __shared__ float As[32 * 68];       // 8.7 KB (padded stride 68)
    __shared__ float out_s[64];

    int t  = threadIdx.x;
    int rt = t / 25;          // 0..7
    int ct = t % 25;          // 0..24
    int n0 = blockIdx.x * 64;

    float accz[8][4];
    float acch[8][4];
    #pragma unroll
    for (int i = 0; i < 8; i++)
        #pragma unroll
        for (int u = 0; u < 4; u++) { accz[i][u] = 0.0f; acch[i][u] = 0.0f; }

    for (int kt = 0; kt < FDIM; kt += 32) {
        __syncthreads();
        for (int idx = t; idx < 32 * NC; idx += 200) {
            int fl = idx / NC, j = idx % NC;
            Bs[idx] = g_M[(kt + fl) * NC + j];
        }
        for (int idx = t; idx < 32 * 64; idx += 200) {
            int fl = idx & 31, nl = idx >> 5;
            int nn = n0 + nl;
            As[fl * 68 + nl] =
                (nn < n) ? g_aggx[(size_t)nn * FDIM + kt + fl] : 0.0f;
        }
        __syncthreads();

        #pragma unroll 4
        for (int f = 0; f < 32; f++) {
            float4 b0 = *(const float4*)&Bs[f * NC + ct * 4];
            float4 b1 = *(const float4*)&Bs[f * NC + HID + ct * 4];
            float4 a0 = *(const float4*)&As[f * 68 + rt * 8];
            float4 a1 = *(const float4*)&As[f * 68 + rt * 8 + 4];
            float a[8] = {a0.x, a0.y, a0.z, a0.w, a1.x, a1.y, a1.z, a1.w};
            float bz[4] = {b0.x, b0.y, b0.z, b0.w};
            float bh[4] = {b1.x, b1.y, b1.z, b1.w};
            #pragma unroll
            for (int i = 0; i < 8; i++) {
                #pragma unroll
                for (int u = 0; u < 4; u++) {
                    accz[i][u] = fmaf(a[i], bz[u], accz[i][u]);
                    acch[i][u] = fmaf(a[i], bh[u], acch[i][u]);
                }
            }
        }
    }

    __syncthreads();
    if (t < 64) out_s[t] = 0.0f;
    __syncthreads();

    float bb0[4], bb1[4], wo[4];
    #pragma unroll
    for (int u = 0; u < 4; u++) {
        int j = ct * 4 + u;
        bb0[u] = g_bias[j];
        bb1[u] = g_bias[j + HID];
        wo[u]  = Wout[j];
    }

    #pragma unroll
    for (int i = 0; i < 8; i++) {
        int r = rt * 8 + i;
        int nn = n0 + r;
        if (nn < n) {
            float p = 0.0f;
            #pragma unroll
            for (int u = 0; u < 4; u++) {
                float z = 1.0f / (1.0f + expf(-(accz[i][u] + bb0[u])));
                float h = tanhf(acch[i][u] + bb1[u]);
                float v = (1.0f - z) * h;
                v = fmaxf(v, 0.0f);
                p = fmaf(v, wo[u], p);
            }
            atomicAdd(&out_s[r], p);
        }
    }
    __syncthreads();
    if (t < 64 && (n0 + t) < n) out[n0 + t] = out_s[t] + bout[0];
}

// ---------------- launch ----------------------------------------------------
extern "C" void kernel_launch(void* const* d_in, const int* in_sizes, int n_in,
                              void* d_out, int out_size) {
    const float* x    = (const float*)d_in[0];
    const int*   ei   = (const int*)d_in[1];     // int32! (JAX canonicalizes int64->int32)
    const float* ew   = (const float*)d_in[2];
    const float* Wcz  = (const float*)d_in[3];
    const float* bcz  = (const float*)d_in[4];
    // d_in[5], d_in[6] = Wcr, bcr  -- unused (H0 = 0)
    const float* Wch  = (const float*)d_in[7];
    const float* bch  = (const float*)d_in[8];
    const float* Wlz  = (const float*)d_in[9];
    const float* blz  = (const float*)d_in[10];
    // d_in[11], d_in[12] = Wlr, blr -- unused
    const float* Wlh  = (const float*)d_in[13];
    const float* blh  = (const float*)d_in[14];
    const float* Wout = (const float*)d_in[15];
    const float* bout = (const float*)d_in[16];
    float*       out  = (float*)d_out;

    int n = in_sizes[0] / FDIM;    // 100000
    int e = in_sizes[2];           // 1600000

    k_deg_init<<<(n + 255) / 256, 256>>>(n);
    k_fuseW<<<(FDIM * NC + 255) / 256, 256>>>(Wcz, Wch, Wlz, Wlh);
    k_fuseB<<<1, NC>>>(bcz, bch, Wlz, Wlh, blz, blh);
    k_deg_acc<<<(e + 255) / 256, 256>>>(ei, ew, e);
    k_dinv<<<(n + 255) / 256, 256>>>(n);
    k_selfloop<<<(n * 32 + 255) / 256, 256>>>(x, n);
    k_edge<<<(e + 7) / 8, 256>>>(ei, ew, x, e);
    k_gemm<<<(n + 63) / 64, 200>>>(Wout, bout, out, n);
}

// round 4
// speedup vs baseline: 1.2630x; 1.2630x over previous
#include <cuda_runtime.h>
#include <cstdint>
#include <math.h>

#define MAXN 100000
#define MAXE 1600000
#define FDIM 128
#define HID  100
#define NC   200                 // 2*HID fused output columns: [z | h]
#define SCAN_BLK 1024
#define NB ((MAXN + SCAN_BLK - 1) / SCAN_BLK)

// ---------------- scratch (static device memory; no runtime allocation) ----
__device__ __align__(16) float g_deg[MAXN];
__device__ __align__(16) float g_dinv[MAXN];
__device__ int   g_cnt[MAXN];
__device__ int   g_off[MAXN + 1];
__device__ int   g_cur[MAXN];
__device__ int   g_bsum[NB];
__device__ __align__(16) unsigned long long g_edge[MAXE];    // packed (src, norm)
__device__ __align__(16) float g_aggx[(size_t)MAXN * FDIM];  // 51.2 MB
__device__ __align__(16) float g_M[FDIM * NC];               // fused weights
__device__ __align__(16) float g_bias[NC];                   // fused biases

// ---------------- init: deg=1 (self loop), cnt=0 ---------------------------
__global__ void k_init(int n) {
    int i = blockIdx.x * blockDim.x + threadIdx.x;
    if (i < n) { g_deg[i] = 1.0f; g_cnt[i] = 0; }
}

// ---------------- per-edge: deg += w, cnt++ ---------------------------------
__global__ void k_deg_acc(const int* __restrict__ ei,
                          const float* __restrict__ ew, int e) {
    int i = blockIdx.x * blockDim.x + threadIdx.x;
    if (i < e) {
        int d = ei[(size_t)e + i];
        atomicAdd(&g_deg[d], ew[i]);
        atomicAdd(&g_cnt[d], 1);
    }
}

__global__ void k_dinv(int n) {
    int i = blockIdx.x * blockDim.x + threadIdx.x;
    if (i < n) {
        float dg = g_deg[i];
        g_dinv[i] = (dg > 0.0f) ? rsqrtf(dg) : 0.0f;
    }
}

// ---------------- exclusive scan of g_cnt -> g_off (3 kernels) -------------
__global__ void k_scan1(int n) {
    __shared__ int s[SCAN_BLK];
    int t = threadIdx.x;
    int idx = blockIdx.x * SCAN_BLK + t;
    int val = (idx < n) ? g_cnt[idx] : 0;
    s[t] = val;
    __syncthreads();
    #pragma unroll
    for (int off = 1; off < SCAN_BLK; off <<= 1) {
        int v = (t >= off) ? s[t - off] : 0;
        __syncthreads();
        s[t] += v;
        __syncthreads();
    }
    if (idx < n) g_off[idx] = s[t] - val;          // exclusive, block-local
    if (t == SCAN_BLK - 1) g_bsum[blockIdx.x] = s[t];
}

__global__ void k_scan2(int nb) {
    if (threadIdx.x == 0) {
        int run = 0;
        for (int b = 0; b < nb; b++) {
            int v = g_bsum[b];
            g_bsum[b] = run;
            run += v;
        }
    }
}

__global__ void k_scan3(int n, int e) {
    int idx = blockIdx.x * blockDim.x + threadIdx.x;
    if (idx < n) {
        int v = g_off[idx] + g_bsum[idx >> 10];
        g_off[idx] = v;
        g_cur[idx] = v;
    }
    if (idx == 0) g_off[n] = e;
}

// ---------------- fill CSR: packed (src, norm) per slot ---------------------
__global__ void k_fill(const int* __restrict__ ei,
                       const float* __restrict__ ew, int e) {
    int i = blockIdx.x * blockDim.x + threadIdx.x;
    if (i >= e) return;
    int s = ei[i];
    int d = ei[(size_t)e + i];
    float nrm = g_dinv[s] * ew[i] * g_dinv[d];
    int pos = atomicAdd(&g_cur[d], 1);
    g_edge[pos] = (unsigned long long)(unsigned)s |
                  ((unsigned long long)__float_as_uint(nrm) << 32);
}

// ---------------- gather: one warp per node, no atomics ---------------------
__global__ void k_gather(const float* __restrict__ x, int n) {
    int w = (blockIdx.x * blockDim.x + threadIdx.x) >> 5;
    int lane = threadIdx.x & 31;
    if (w >= n) return;
    int beg = g_off[w];
    int end = g_off[w + 1];
    float s = g_dinv[w];
    float s2 = s * s;
    float4 acc = ((const float4*)(x + (size_t)w * FDIM))[lane];
    acc.x *= s2; acc.y *= s2; acc.z *= s2; acc.w *= s2;
    #pragma unroll 2
    for (int j = beg; j < end; j++) {
        unsigned long long m = g_edge[j];
        int src = (int)(unsigned)m;
        float nrm = __uint_as_float((unsigned)(m >> 32));
        float4 v = ((const float4*)(x + (size_t)src * FDIM))[lane];
        acc.x = fmaf(v.x, nrm, acc.x);
        acc.y = fmaf(v.y, nrm, acc.y);
        acc.z = fmaf(v.z, nrm, acc.z);
        acc.w = fmaf(v.w, nrm, acc.w);
    }
    ((float4*)(g_aggx + (size_t)w * FDIM))[lane] = acc;
}

// ---------------- fused weights: M = [Wcz@Wlz[:H] | Wch@Wlh[:H]] -----------
__global__ void k_fuseW(const float* __restrict__ Wcz,
                        const float* __restrict__ Wch,
                        const float* __restrict__ Wlz,
                        const float* __restrict__ Wlh) {
    int id = blockIdx.x * blockDim.x + threadIdx.x;
    if (id >= FDIM * NC) return;
    int f = id / NC, j = id % NC;
    const float* A = (j < HID) ? Wcz : Wch;
    const float* B = (j < HID) ? Wlz : Wlh;   // rows [0,HID) of [2H,H]
    int jj = (j < HID) ? j : j - HID;
    float s = 0.0f;
    #pragma unroll 4
    for (int t = 0; t < HID; t++)
        s += A[f * HID + t] * B[t * HID + jj];
    g_M[id] = s;
}

__global__ void k_fuseB(const float* __restrict__ bcz,
                        const float* __restrict__ bch,
                        const float* __restrict__ Wlz,
                        const float* __restrict__ Wlh,
                        const float* __restrict__ blz,
                        const float* __restrict__ blh) {
    int j = threadIdx.x;
    if (j >= NC) return;
    const float* bc = (j < HID) ? bcz : bch;
    const float* Wl = (j < HID) ? Wlz : Wlh;
    const float* bl = (j < HID) ? blz : blh;
    int jj = (j < HID) ? j : j - HID;
    float s = bl[jj];
    for (int t = 0; t < HID; t++)
        s += bc[t] * Wl[t * HID + jj];
    g_bias[j] = s;
}

// ---------------- fused GEMM + TGCN epilogue + output GEMV -----------------
__global__ void __launch_bounds__(200) k_gemm(const float* __restrict__ Wout,
                                              const float* __restrict__ bout,
                                              float* __restrict__ out, int n) {
    __shared__ float Bs[32 * NC];       // 25.6 KB
    __shared__ float As[32 * 68];       // 8.7 KB (padded stride 68)
    __shared__ float out_s[64];

    int t  = threadIdx.x;
    int rt = t / 25;          // 0..7
    int ct = t % 25;          // 0..24
    int n0 = blockIdx.x * 64;

    float accz[8][4];
    float acch[8][4];
    #pragma unroll
    for (int i = 0; i < 8; i++)
        #pragma unroll
        for (int u = 0; u < 4; u++) { accz[i][u] = 0.0f; acch[i][u] = 0.0f; }

    for (int kt = 0; kt < FDIM; kt += 32) {
        __syncthreads();
        for (int idx = t; idx < 32 * NC; idx += 200) {
            int fl = idx / NC, j = idx % NC;
            Bs[idx] = g_M[(kt + fl) * NC + j];
        }
        for (int idx = t; idx < 32 * 64; idx += 200) {
            int fl = idx & 31, nl = idx >> 5;
            int nn = n0 + nl;
            As[fl * 68 + nl] =
                (nn < n) ? g_aggx[(size_t)nn * FDIM + kt + fl] : 0.0f;
        }
        __syncthreads();

        #pragma unroll 4
        for (int f = 0; f < 32; f++) {
            float4 b0 = *(const float4*)&Bs[f * NC + ct * 4];
            float4 b1 = *(const float4*)&Bs[f * NC + HID + ct * 4];
            float4 a0 = *(const float4*)&As[f * 68 + rt * 8];
            float4 a1 = *(const float4*)&As[f * 68 + rt * 8 + 4];
            float a[8] = {a0.x, a0.y, a0.z, a0.w, a1.x, a1.y, a1.z, a1.w};
            float bz[4] = {b0.x, b0.y, b0.z, b0.w};
            float bh[4] = {b1.x, b1.y, b1.z, b1.w};
            #pragma unroll
            for (int i = 0; i < 8; i++) {
                #pragma unroll
                for (int u = 0; u < 4; u++) {
                    accz[i][u] = fmaf(a[i], bz[u], accz[i][u]);
                    acch[i][u] = fmaf(a[i], bh[u], acch[i][u]);
                }
            }
        }
    }

    __syncthreads();
    if (t < 64) out_s[t] = 0.0f;
    __syncthreads();

    float bb0[4], bb1[4], wo[4];
    #pragma unroll
    for (int u = 0; u < 4; u++) {
        int j = ct * 4 + u;
        bb0[u] = g_bias[j];
        bb1[u] = g_bias[j + HID];
        wo[u]  = Wout[j];
    }

    #pragma unroll
    for (int i = 0; i < 8; i++) {
        int r = rt * 8 + i;
        int nn = n0 + r;
        if (nn < n) {
            float p = 0.0f;
            #pragma unroll
            for (int u = 0; u < 4; u++) {
                float z = 1.0f / (1.0f + expf(-(accz[i][u] + bb0[u])));
                float h = tanhf(acch[i][u] + bb1[u]);
                float v = (1.0f - z) * h;
                v = fmaxf(v, 0.0f);
                p = fmaf(v, wo[u], p);
            }
            atomicAdd(&out_s[r], p);
        }
    }
    __syncthreads();
    if (t < 64 && (n0 + t) < n) out[n0 + t] = out_s[t] + bout[0];
}

// ---------------- launch ----------------------------------------------------
extern "C" void kernel_launch(void* const* d_in, const int* in_sizes, int n_in,
                              void* d_out, int out_size) {
    const float* x    = (const float*)d_in[0];
    const int*   ei   = (const int*)d_in[1];     // int32 (JAX canonicalizes)
    const float* ew   = (const float*)d_in[2];
    const float* Wcz  = (const float*)d_in[3];
    const float* bcz  = (const float*)d_in[4];
    const float* Wch  = (const float*)d_in[7];
    const float* bch  = (const float*)d_in[8];
    const float* Wlz  = (const float*)d_in[9];
    const float* blz  = (const float*)d_in[10];
    const float* Wlh  = (const float*)d_in[13];
    const float* blh  = (const float*)d_in[14];
    const float* Wout = (const float*)d_in[15];
    const float* bout = (const float*)d_in[16];
    float*       out  = (float*)d_out;

    int n = in_sizes[0] / FDIM;    // 100000
    int e = in_sizes[2];           // 1600000
    int nb = (n + SCAN_BLK - 1) / SCAN_BLK;

    k_init<<<(n + 255) / 256, 256>>>(n);
    k_fuseW<<<(FDIM * NC + 255) / 256, 256>>>(Wcz, Wch, Wlz, Wlh);
    k_fuseB<<<1, NC>>>(bcz, bch, Wlz, Wlh, blz, blh);
    k_deg_acc<<<(e + 255) / 256, 256>>>(ei, ew, e);
    k_dinv<<<(n + 255) / 256, 256>>>(n);
    k_scan1<<<nb, SCAN_BLK>>>(n);
    k_scan2<<<1, 32>>>(nb);
    k_scan3<<<(n + 255) / 256, 256>>>(n, e);
    k_fill<<<(e + 255) / 256, 256>>>(ei, ew, e);
    k_gather<<<(n * 32 + 255) / 256, 256>>>(x, n);
    k_gemm<<<(n + 63) / 64, 200>>>(Wout, bout, out, n);
}

// round 5
// speedup vs baseline: 2.3329x; 1.8471x over previous
#include <cuda_runtime.h>
#include <cstdint>
#include <math.h>

#define MAXN 100000
#define MAXE 1600000
#define FDIM 128
#define HID  100
#define NC   200                 // 2*HID fused output columns: [z | h]
#define SCAN_BLK 1024
#define NB ((MAXN + SCAN_BLK - 1) / SCAN_BLK)

// tensor-gemm smem geometry
#define AS_STRIDE 132            // 128 k + 4 pad (bank-conflict-free frags)
#define BS_STRIDE 204            // 200 n + 4 pad
#define SMEM_BYTES ((128 * AS_STRIDE + FDIM * BS_STRIDE) * 4)   // 172,032

// ---------------- scratch (static device memory; no runtime allocation) ----
__device__ __align__(16) float g_deg[MAXN];
__device__ __align__(16) float g_dinv[MAXN];
__device__ int   g_cnt[MAXN];
__device__ int   g_off[MAXN + 1];
__device__ int   g_cur[MAXN];
__device__ int   g_bsum[NB];
__device__ __align__(16) unsigned long long g_edge[MAXE];    // packed (src, norm)
__device__ __align__(16) float g_aggx[(size_t)MAXN * FDIM];  // 51.2 MB
__device__ __align__(16) float g_M[FDIM * NC];               // fused weights
__device__ __align__(16) float g_bias[NC];                   // fused biases

__device__ __forceinline__ float tanhfast(float x) {
    float y;
    asm("tanh.approx.f32 %0, %1;" : "=f"(y) : "f"(x));
    return y;
}
__device__ __forceinline__ unsigned to_tf32(float x) {
    unsigned u;
    asm("cvt.rna.tf32.f32 %0, %1;" : "=r"(u) : "f"(x));
    return u;
}
__device__ __forceinline__ void mma_tf32(float* c, const unsigned* a,
                                         unsigned b0, unsigned b1) {
    asm volatile(
        "mma.sync.aligned.m16n8k8.row.col.f32.tf32.tf32.f32 "
        "{%0,%1,%2,%3},{%4,%5,%6,%7},{%8,%9},{%0,%1,%2,%3};"
        : "+f"(c[0]), "+f"(c[1]), "+f"(c[2]), "+f"(c[3])
        : "r"(a[0]), "r"(a[1]), "r"(a[2]), "r"(a[3]), "r"(b0), "r"(b1));
}

// ---------------- init: deg=1 (self loop), cnt=0 ---------------------------
__global__ void k_init(int n) {
    int i = blockIdx.x * blockDim.x + threadIdx.x;
    if (i < n) { g_deg[i] = 1.0f; g_cnt[i] = 0; }
}

__global__ void k_deg_acc(const int* __restrict__ ei,
                          const float* __restrict__ ew, int e) {
    int i = blockIdx.x * blockDim.x + threadIdx.x;
    if (i < e) {
        int d = ei[(size_t)e + i];
        atomicAdd(&g_deg[d], ew[i]);
        atomicAdd(&g_cnt[d], 1);
    }
}

__global__ void k_dinv(int n) {
    int i = blockIdx.x * blockDim.x + threadIdx.x;
    if (i < n) {
        float dg = g_deg[i];
        g_dinv[i] = (dg > 0.0f) ? rsqrtf(dg) : 0.0f;
    }
}

// ---------------- exclusive scan of g_cnt -> g_off -------------------------
__global__ void k_scan1(int n) {
    __shared__ int s[SCAN_BLK];
    int t = threadIdx.x;
    int idx = blockIdx.x * SCAN_BLK + t;
    int val = (idx < n) ? g_cnt[idx] : 0;
    s[t] = val;
    __syncthreads();
    #pragma unroll
    for (int off = 1; off < SCAN_BLK; off <<= 1) {
        int v = (t >= off) ? s[t - off] : 0;
        __syncthreads();
        s[t] += v;
        __syncthreads();
    }
    if (idx < n) g_off[idx] = s[t] - val;          // exclusive, block-local
    if (t == SCAN_BLK - 1) g_bsum[blockIdx.x] = s[t];
}

// parallel scan of block sums (NB <= 128)
__global__ void k_scan2(int nb) {
    __shared__ int s[128];
    int t = threadIdx.x;
    int v = (t < nb) ? g_bsum[t] : 0;
    s[t] = v;
    __syncthreads();
    #pragma unroll
    for (int off = 1; off < 128; off <<= 1) {
        int u = (t >= off) ? s[t - off] : 0;
        __syncthreads();
        s[t] += u;
        __syncthreads();
    }
    if (t < nb) g_bsum[t] = s[t] - v;              // exclusive
}

__global__ void k_scan3(int n, int e) {
    int idx = blockIdx.x * blockDim.x + threadIdx.x;
    if (idx < n) {
        int v = g_off[idx] + g_bsum[idx >> 10];
        g_off[idx] = v;
        g_cur[idx] = v;
    }
    if (idx == 0) g_off[n] = e;
}

// ---------------- fill CSR: packed (src, norm) per slot ---------------------
__global__ void k_fill(const int* __restrict__ ei,
                       const float* __restrict__ ew, int e) {
    int i = blockIdx.x * blockDim.x + threadIdx.x;
    if (i >= e) return;
    int s = ei[i];
    int d = ei[(size_t)e + i];
    float nrm = g_dinv[s] * ew[i] * g_dinv[d];
    int pos = atomicAdd(&g_cur[d], 1);
    g_edge[pos] = (unsigned long long)(unsigned)s |
                  ((unsigned long long)__float_as_uint(nrm) << 32);
}

// ---------------- gather: one warp per node, unroll-4 for MLP ---------------
__global__ void k_gather(const float* __restrict__ x, int n) {
    int w = (blockIdx.x * blockDim.x + threadIdx.x) >> 5;
    int lane = threadIdx.x & 31;
    if (w >= n) return;
    int beg = g_off[w];
    int end = g_off[w + 1];
    float s = g_dinv[w];
    float s2 = s * s;
    float4 acc = ((const float4*)(x + (size_t)w * FDIM))[lane];
    acc.x *= s2; acc.y *= s2; acc.z *= s2; acc.w *= s2;

    int j = beg;
    int m4 = beg + ((end - beg) & ~3);
    for (; j < m4; j += 4) {
        unsigned long long m0 = g_edge[j];
        unsigned long long m1 = g_edge[j + 1];
        unsigned long long m2 = g_edge[j + 2];
        unsigned long long m3 = g_edge[j + 3];
        float4 v0 = ((const float4*)(x + (size_t)(unsigned)m0 * FDIM))[lane];
        float4 v1 = ((const float4*)(x + (size_t)(unsigned)m1 * FDIM))[lane];
        float4 v2 = ((const float4*)(x + (size_t)(unsigned)m2 * FDIM))[lane];
        float4 v3 = ((const float4*)(x + (size_t)(unsigned)m3 * FDIM))[lane];
        float n0 = __uint_as_float((unsigned)(m0 >> 32));
        float n1 = __uint_as_float((unsigned)(m1 >> 32));
        float n2 = __uint_as_float((unsigned)(m2 >> 32));
        float n3 = __uint_as_float((unsigned)(m3 >> 32));
        acc.x = fmaf(v0.x, n0, acc.x); acc.y = fmaf(v0.y, n0, acc.y);
        acc.z = fmaf(v0.z, n0, acc.z); acc.w = fmaf(v0.w, n0, acc.w);
        acc.x = fmaf(v1.x, n1, acc.x); acc.y = fmaf(v1.y, n1, acc.y);
        acc.z = fmaf(v1.z, n1, acc.z); acc.w = fmaf(v1.w, n1, acc.w);
        acc.x = fmaf(v2.x, n2, acc.x); acc.y = fmaf(v2.y, n2, acc.y);
        acc.z = fmaf(v2.z, n2, acc.z); acc.w = fmaf(v2.w, n2, acc.w);
        acc.x = fmaf(v3.x, n3, acc.x); acc.y = fmaf(v3.y, n3, acc.y);
        acc.z = fmaf(v3.z, n3, acc.z); acc.w = fmaf(v3.w, n3, acc.w);
    }
    for (; j < end; j++) {
        unsigned long long m = g_edge[j];
        float nrm = __uint_as_float((unsigned)(m >> 32));
        float4 v = ((const float4*)(x + (size_t)(unsigned)m * FDIM))[lane];
        acc.x = fmaf(v.x, nrm, acc.x); acc.y = fmaf(v.y, nrm, acc.y);
        acc.z = fmaf(v.z, nrm, acc.z); acc.w = fmaf(v.w, nrm, acc.w);
    }
    ((float4*)(g_aggx + (size_t)w * FDIM))[lane] = acc;
}

// ---------------- fused weights: M = [Wcz@Wlz[:H] | Wch@Wlh[:H]] -----------
__global__ void k_fuseW(const float* __restrict__ Wcz,
                        const float* __restrict__ Wch,
                        const float* __restrict__ Wlz,
                        const float* __restrict__ Wlh) {
    int id = blockIdx.x * blockDim.x + threadIdx.x;
    if (id >= FDIM * NC) return;
    int f = id / NC, j = id % NC;
    const float* A = (j < HID) ? Wcz : Wch;
    const float* B = (j < HID) ? Wlz : Wlh;   // rows [0,HID) of [2H,H]
    int jj = (j < HID) ? j : j - HID;
    float s = 0.0f;
    #pragma unroll 4
    for (int t = 0; t < HID; t++)
        s += A[f * HID + t] * B[t * HID + jj];
    g_M[id] = s;
}

__global__ void k_fuseB(const float* __restrict__ bcz,
                        const float* __restrict__ bch,
                        const float* __restrict__ Wlz,
                        const float* __restrict__ Wlh,
                        const float* __restrict__ blz,
                        const float* __restrict__ blh) {
    int j = threadIdx.x;
    if (j >= NC) return;
    const float* bc = (j < HID) ? bcz : bch;
    const float* Wl = (j < HID) ? Wlz : Wlh;
    const float* bl = (j < HID) ? blz : blh;
    int jj = (j < HID) ? j : j - HID;
    float s = bl[jj];
    for (int t = 0; t < HID; t++)
        s += bc[t] * Wl[t * HID + jj];
    g_bias[j] = s;
}

// ---------------- tf32 tensor-core GEMM + fused TGCN epilogue ---------------
// per block: 128 rows x 200 cols, K=128. 8 warps: mw=w&3 (32 rows each),
// nw=w>>2 (13 n-tiles starting at col nw*96; tiles 96..103 overlap benignly).
__global__ void __launch_bounds__(256, 1)
k_tgemm(const float* __restrict__ Wout, const float* __restrict__ bout,
        float* __restrict__ out, int n) {
    extern __shared__ unsigned smem[];
    unsigned* As = smem;                       // [128][AS_STRIDE]
    unsigned* Bs = smem + 128 * AS_STRIDE;     // [FDIM][BS_STRIDE], reused as C

    __shared__ float sbias[NC];
    __shared__ float swout[HID];
    __shared__ float sbout;

    int tid = threadIdx.x;
    int n0 = blockIdx.x * 128;

    if (tid < NC)  sbias[tid] = g_bias[tid];
    if (tid < HID) swout[tid] = Wout[tid];
    if (tid == 0)  sbout = bout[0];

    // cooperative load A tile (128 x 128) as tf32 bits
    for (int idx = tid; idx < 128 * 32; idx += 256) {
        int r = idx >> 5, c4 = idx & 31;
        int nn = n0 + r;
        float4 v = (nn < n) ? ((const float4*)g_aggx)[(size_t)nn * 32 + c4]
                            : make_float4(0.f, 0.f, 0.f, 0.f);
        unsigned* dst = &As[r * AS_STRIDE + c4 * 4];
        dst[0] = to_tf32(v.x); dst[1] = to_tf32(v.y);
        dst[2] = to_tf32(v.z); dst[3] = to_tf32(v.w);
    }
    // cooperative load B = g_M (128 x 200) as tf32 bits
    for (int idx = tid; idx < FDIM * 50; idx += 256) {
        int k = idx / 50, c4 = idx % 50;
        float4 v = ((const float4*)g_M)[k * 50 + c4];
        unsigned* dst = &Bs[k * BS_STRIDE + c4 * 4];
        dst[0] = to_tf32(v.x); dst[1] = to_tf32(v.y);
        dst[2] = to_tf32(v.z); dst[3] = to_tf32(v.w);
    }
    __syncthreads();

    int lane = tid & 31, w = tid >> 5;
    int mw = w & 3, nw = w >> 2;
    int rbase = mw * 32;
    int nbase = nw * 96;
    int lr = lane >> 2, lc = lane & 3;

    float c[2][13][4];
    #pragma unroll
    for (int ms = 0; ms < 2; ms++)
        #pragma unroll
        for (int t = 0; t < 13; t++)
            #pragma unroll
            for (int u = 0; u < 4; u++) c[ms][t][u] = 0.0f;

    #pragma unroll
    for (int ks = 0; ks < 16; ks++) {
        int k0 = ks * 8;
        unsigned a[2][4];
        #pragma unroll
        for (int ms = 0; ms < 2; ms++) {
            int r0 = rbase + ms * 16 + lr;
            a[ms][0] = As[r0 * AS_STRIDE + k0 + lc];
            a[ms][1] = As[(r0 + 8) * AS_STRIDE + k0 + lc];
            a[ms][2] = As[r0 * AS_STRIDE + k0 + lc + 4];
            a[ms][3] = As[(r0 + 8) * AS_STRIDE + k0 + lc + 4];
        }
        #pragma unroll
        for (int t = 0; t < 13; t++) {
            int ncol = nbase + t * 8 + lr;
            unsigned b0 = Bs[(k0 + lc) * BS_STRIDE + ncol];
            unsigned b1 = Bs[(k0 + lc + 4) * BS_STRIDE + ncol];
            mma_tf32(c[0][t], a[0], b0, b1);
            mma_tf32(c[1][t], a[1], b0, b1);
        }
    }

    // write C frags into smem (reuse Bs region; overlap tiles write equal bits)
    __syncthreads();
    float* Cs = (float*)Bs;
    #pragma unroll
    for (int ms = 0; ms < 2; ms++) {
        #pragma unroll
        for (int t = 0; t < 13; t++) {
            int rr = rbase + ms * 16 + lr;
            int cc = nbase + t * 8 + lc * 2;
            *(float2*)&Cs[rr * BS_STRIDE + cc] =
                make_float2(c[ms][t][0], c[ms][t][1]);
            *(float2*)&Cs[(rr + 8) * BS_STRIDE + cc] =
                make_float2(c[ms][t][2], c[ms][t][3]);
        }
    }
    __syncthreads();

    // epilogue: thread pair per row; z = sigmoid, h = tanh, out = dot with Wout
    int r = tid >> 1, half = tid & 1;
    int nn = n0 + r;
    const float* Cr = &Cs[r * BS_STRIDE];
    float sum = 0.0f;
    #pragma unroll 2
    for (int jj = 0; jj < 50; jj++) {
        int j = half * 50 + jj;
        float zr = Cr[j] + sbias[j];
        float hr = Cr[HID + j] + sbias[HID + j];
        float omz = 0.5f * (1.0f - tanhfast(0.5f * zr));   // 1 - sigmoid(zr)
        float v = fmaxf(omz * tanhfast(hr), 0.0f);
        sum = fmaf(v, swout[j], sum);
    }
    sum += __shfl_down_sync(0xffffffffu, sum, 1);
    if (half == 0 && nn < n) out[nn] = sum + sbout;
}

// ---------------- launch ----------------------------------------------------
extern "C" void kernel_launch(void* const* d_in, const int* in_sizes, int n_in,
                              void* d_out, int out_size) {
    const float* x    = (const float*)d_in[0];
    const int*   ei   = (const int*)d_in[1];     // int32 (JAX canonicalizes)
    const float* ew   = (const float*)d_in[2];
    const float* Wcz  = (const float*)d_in[3];
    const float* bcz  = (const float*)d_in[4];
    const float* Wch  = (const float*)d_in[7];
    const float* bch  = (const float*)d_in[8];
    const float* Wlz  = (const float*)d_in[9];
    const float* blz  = (const float*)d_in[10];
    const float* Wlh  = (const float*)d_in[13];
    const float* blh  = (const float*)d_in[14];
    const float* Wout = (const float*)d_in[15];
    const float* bout = (const float*)d_in[16];
    float*       out  = (float*)d_out;

    int n = in_sizes[0] / FDIM;    // 100000
    int e = in_sizes[2];           // 1600000
    int nb = (n + SCAN_BLK - 1) / SCAN_BLK;

    static bool attr_set = false;
    if (!attr_set) {
        cudaFuncSetAttribute(k_tgemm,
                             cudaFuncAttributeMaxDynamicSharedMemorySize,
                             SMEM_BYTES);
        attr_set = true;
    }

    k_init<<<(n + 255) / 256, 256>>>(n);
    k_fuseW<<<(FDIM * NC + 255) / 256, 256>>>(Wcz, Wch, Wlz, Wlh);
    k_fuseB<<<1, NC>>>(bcz, bch, Wlz, Wlh, blz, blh);
    k_deg_acc<<<(e + 255) / 256, 256>>>(ei, ew, e);
    k_dinv<<<(n + 255) / 256, 256>>>(n);
    k_scan1<<<nb, SCAN_BLK>>>(n);
    k_scan2<<<1, 128>>>(nb);
    k_scan3<<<(n + 255) / 256, 256>>>(n, e);
    k_fill<<<(e + 255) / 256, 256>>>(ei, ew, e);
    k_gather<<<(n * 32 + 255) / 256, 256>>>(x, n);
    k_tgemm<<<(n + 127) / 128, 256, SMEM_BYTES>>>(Wout, bout, out, n);
}

// round 6
// speedup vs baseline: 2.5198x; 1.0801x over previous
#include <cuda_runtime.h>
#include <cuda_fp16.h>
#include <cstdint>
#include <math.h>

#define MAXN 100000
#define MAXE 1600000
#define FDIM 128
#define HID  100
#define NC   200                 // 2*HID fused output columns: [z | h]
#define SCAN_BLK 1024
#define NB ((MAXN + SCAN_BLK - 1) / SCAN_BLK)

// tensor-gemm smem geometry
#define AS_STRIDE 132            // 128 k + 4 pad
#define BS_STRIDE 204            // 200 n + 4 pad
#define SMEM_BYTES ((128 * AS_STRIDE + FDIM * BS_STRIDE) * 4)   // 172,032

// ---------------- scratch (static device memory; no runtime allocation) ----
__device__ __align__(16) float g_deg[MAXN];
__device__ __align__(16) float g_dinv[MAXN];
__device__ int   g_cnt[MAXN];
__device__ int   g_off[MAXN + 1];
__device__ int   g_cur[MAXN];
__device__ int   g_bsum[NB];
__device__ __align__(16) unsigned long long g_edge[MAXE];    // packed (src, norm)
__device__ __align__(16) uint2 g_xh[(size_t)MAXN * 32];      // x as fp16, 25.6 MB
__device__ __align__(16) uint2 g_agg16[(size_t)MAXN * 32];   // aggx as fp16, 25.6 MB
__device__ __align__(16) float g_M[FDIM * NC];               // fused weights
__device__ __align__(16) float g_bias[NC];                   // fused biases

__device__ __forceinline__ float tanhfast(float x) {
    float y;
    asm("tanh.approx.f32 %0, %1;" : "=f"(y) : "f"(x));
    return y;
}
__device__ __forceinline__ unsigned to_tf32(float x) {
    unsigned u;
    asm("cvt.rna.tf32.f32 %0, %1;" : "=r"(u) : "f"(x));
    return u;
}
__device__ __forceinline__ void mma_tf32(float* c, const unsigned* a,
                                         unsigned b0, unsigned b1) {
    asm volatile(
        "mma.sync.aligned.m16n8k8.row.col.f32.tf32.tf32.f32 "
        "{%0,%1,%2,%3},{%4,%5,%6,%7},{%8,%9},{%0,%1,%2,%3};"
        : "+f"(c[0]), "+f"(c[1]), "+f"(c[2]), "+f"(c[3])
        : "r"(a[0]), "r"(a[1]), "r"(a[2]), "r"(a[3]), "r"(b0), "r"(b1));
}
__device__ __forceinline__ float4 h4_to_f4(uint2 u) {
    float2 fa = __half22float2(*(__half2*)&u.x);
    float2 fb = __half22float2(*(__half2*)&u.y);
    return make_float4(fa.x, fa.y, fb.x, fb.y);
}

// ---------------- init: deg=1 (self loop), cnt=0 ---------------------------
__global__ void k_init(int n) {
    int i = blockIdx.x * blockDim.x + threadIdx.x;
    if (i < n) { g_deg[i] = 1.0f; g_cnt[i] = 0; }
}

// ---------------- x -> fp16 --------------------------------------------------
__global__ void k_prep(const float* __restrict__ x, int n) {
    int i = blockIdx.x * blockDim.x + threadIdx.x;
    if (i >= n * 32) return;
    float4 v = ((const float4*)x)[i];
    uint2 u;
    *(__half2*)&u.x = __floats2half2_rn(v.x, v.y);
    *(__half2*)&u.y = __floats2half2_rn(v.z, v.w);
    g_xh[i] = u;
}

__global__ void k_deg_acc(const int* __restrict__ ei,
                          const float* __restrict__ ew, int e) {
    int i = blockIdx.x * blockDim.x + threadIdx.x;
    if (i < e) {
        int d = ei[(size_t)e + i];
        atomicAdd(&g_deg[d], ew[i]);
        atomicAdd(&g_cnt[d], 1);
    }
}

__global__ void k_dinv(int n) {
    int i = blockIdx.x * blockDim.x + threadIdx.x;
    if (i < n) {
        float dg = g_deg[i];
        g_dinv[i] = (dg > 0.0f) ? rsqrtf(dg) : 0.0f;
    }
}

// ---------------- exclusive scan of g_cnt -> g_off -------------------------
__global__ void k_scan1(int n) {
    __shared__ int s[SCAN_BLK];
    int t = threadIdx.x;
    int idx = blockIdx.x * SCAN_BLK + t;
    int val = (idx < n) ? g_cnt[idx] : 0;
    s[t] = val;
    __syncthreads();
    #pragma unroll
    for (int off = 1; off < SCAN_BLK; off <<= 1) {
        int v = (t >= off) ? s[t - off] : 0;
        __syncthreads();
        s[t] += v;
        __syncthreads();
    }
    if (idx < n) g_off[idx] = s[t] - val;          // exclusive, block-local
    if (t == SCAN_BLK - 1) g_bsum[blockIdx.x] = s[t];
}

__global__ void k_scan2(int nb) {
    __shared__ int s[128];
    int t = threadIdx.x;
    int v = (t < nb) ? g_bsum[t] : 0;
    s[t] = v;
    __syncthreads();
    #pragma unroll
    for (int off = 1; off < 128; off <<= 1) {
        int u = (t >= off) ? s[t - off] : 0;
        __syncthreads();
        s[t] += u;
        __syncthreads();
    }
    if (t < nb) g_bsum[t] = s[t] - v;              // exclusive
}

__global__ void k_scan3(int n, int e) {
    int idx = blockIdx.x * blockDim.x + threadIdx.x;
    if (idx < n) {
        int v = g_off[idx] + g_bsum[idx >> 10];
        g_off[idx] = v;
        g_cur[idx] = v;
    }
    if (idx == 0) g_off[n] = e;
}

// ---------------- fill CSR: packed (src, norm) per slot ---------------------
__global__ void k_fill(const int* __restrict__ ei,
                       const float* __restrict__ ew, int e) {
    int i = blockIdx.x * blockDim.x + threadIdx.x;
    if (i >= e) return;
    int s = ei[i];
    int d = ei[(size_t)e + i];
    float nrm = g_dinv[s] * ew[i] * g_dinv[d];
    int pos = atomicAdd(&g_cur[d], 1);
    g_edge[pos] = (unsigned long long)(unsigned)s |
                  ((unsigned long long)__float_as_uint(nrm) << 32);
}

// ---------------- gather: one warp per node, fp16 payload, fp32 accum -------
__global__ void k_gather(int n) {
    int w = (blockIdx.x * blockDim.x + threadIdx.x) >> 5;
    int lane = threadIdx.x & 31;
    if (w >= n) return;
    int beg = g_off[w];
    int end = g_off[w + 1];
    float s = g_dinv[w];
    float s2 = s * s;
    float4 acc = h4_to_f4(g_xh[(size_t)w * 32 + lane]);
    acc.x *= s2; acc.y *= s2; acc.z *= s2; acc.w *= s2;

    int j = beg;
    int m4 = beg + ((end - beg) & ~3);
    for (; j < m4; j += 4) {
        unsigned long long m0 = g_edge[j];
        unsigned long long m1 = g_edge[j + 1];
        unsigned long long m2 = g_edge[j + 2];
        unsigned long long m3 = g_edge[j + 3];
        float4 v0 = h4_to_f4(g_xh[(size_t)(unsigned)m0 * 32 + lane]);
        float4 v1 = h4_to_f4(g_xh[(size_t)(unsigned)m1 * 32 + lane]);
        float4 v2 = h4_to_f4(g_xh[(size_t)(unsigned)m2 * 32 + lane]);
        float4 v3 = h4_to_f4(g_xh[(size_t)(unsigned)m3 * 32 + lane]);
        float n0 = __uint_as_float((unsigned)(m0 >> 32));
        float n1 = __uint_as_float((unsigned)(m1 >> 32));
        float n2 = __uint_as_float((unsigned)(m2 >> 32));
        float n3 = __uint_as_float((unsigned)(m3 >> 32));
        acc.x = fmaf(v0.x, n0, acc.x); acc.y = fmaf(v0.y, n0, acc.y);
        acc.z = fmaf(v0.z, n0, acc.z); acc.w = fmaf(v0.w, n0, acc.w);
        acc.x = fmaf(v1.x, n1, acc.x); acc.y = fmaf(v1.y, n1, acc.y);
        acc.z = fmaf(v1.z, n1, acc.z); acc.w = fmaf(v1.w, n1, acc.w);
        acc.x = fmaf(v2.x, n2, acc.x); acc.y = fmaf(v2.y, n2, acc.y);
        acc.z = fmaf(v2.z, n2, acc.z); acc.w = fmaf(v2.w, n2, acc.w);
        acc.x = fmaf(v3.x, n3, acc.x); acc.y = fmaf(v3.y, n3, acc.y);
        acc.z = fmaf(v3.z, n3, acc.z); acc.w = fmaf(v3.w, n3, acc.w);
    }
    for (; j < end; j++) {
        unsigned long long m = g_edge[j];
        float nrm = __uint_as_float((unsigned)(m >> 32));
        float4 v = h4_to_f4(g_xh[(size_t)(unsigned)m * 32 + lane]);
        acc.x = fmaf(v.x, nrm, acc.x); acc.y = fmaf(v.y, nrm, acc.y);
        acc.z = fmaf(v.z, nrm, acc.z); acc.w = fmaf(v.w, nrm, acc.w);
    }
    uint2 u;
    *(__half2*)&u.x = __floats2half2_rn(acc.x, acc.y);
    *(__half2*)&u.y = __floats2half2_rn(acc.z, acc.w);
    g_agg16[(size_t)w * 32 + lane] = u;
}

// ---------------- fused weights: M = [Wcz@Wlz[:H] | Wch@Wlh[:H]] -----------
__global__ void k_fuseW(const float* __restrict__ Wcz,
                        const float* __restrict__ Wch,
                        const float* __restrict__ Wlz,
                        const float* __restrict__ Wlh) {
    int id = blockIdx.x * blockDim.x + threadIdx.x;
    if (id >= FDIM * NC) return;
    int f = id / NC, j = id % NC;
    const float* A = (j < HID) ? Wcz : Wch;
    const float* B = (j < HID) ? Wlz : Wlh;   // rows [0,HID) of [2H,H]
    int jj = (j < HID) ? j : j - HID;
    float s = 0.0f;
    #pragma unroll 4
    for (int t = 0; t < HID; t++)
        s += A[f * HID + t] * B[t * HID + jj];
    g_M[id] = s;
}

__global__ void k_fuseB(const float* __restrict__ bcz,
                        const float* __restrict__ bch,
                        const float* __restrict__ Wlz,
                        const float* __restrict__ Wlh,
                        const float* __restrict__ blz,
                        const float* __restrict__ blh) {
    int j = threadIdx.x;
    if (j >= NC) return;
    const float* bc = (j < HID) ? bcz : bch;
    const float* Wl = (j < HID) ? Wlz : Wlh;
    const float* bl = (j < HID) ? blz : blh;
    int jj = (j < HID) ? j : j - HID;
    float s = bl[jj];
    for (int t = 0; t < HID; t++)
        s += bc[t] * Wl[t * HID + jj];
    g_bias[j] = s;
}

// ---------------- tf32 tensor-core GEMM + fused TGCN epilogue ---------------
__global__ void __launch_bounds__(256, 1)
k_tgemm(const float* __restrict__ Wout, const float* __restrict__ bout,
        float* __restrict__ out, int n) {
    extern __shared__ unsigned smem[];
    unsigned* As = smem;                       // [128][AS_STRIDE]
    unsigned* Bs = smem + 128 * AS_STRIDE;     // [FDIM][BS_STRIDE], reused as C

    __shared__ float sbias[NC];
    __shared__ float swout[HID];
    __shared__ float sbout;

    int tid = threadIdx.x;
    int n0 = blockIdx.x * 128;

    if (tid < NC)  sbias[tid] = g_bias[tid];
    if (tid < HID) swout[tid] = Wout[tid];
    if (tid == 0)  sbout = bout[0];

    // cooperative load A tile (128 x 128) from fp16 aggx (fp16 -> tf32 exact)
    for (int idx = tid; idx < 128 * 32; idx += 256) {
        int r = idx >> 5, c4 = idx & 31;
        int nn = n0 + r;
        uint2 u = (nn < n) ? g_agg16[(size_t)nn * 32 + c4] : make_uint2(0u, 0u);
        float4 v = h4_to_f4(u);
        unsigned* dst = &As[r * AS_STRIDE + c4 * 4];
        dst[0] = to_tf32(v.x); dst[1] = to_tf32(v.y);
        dst[2] = to_tf32(v.z); dst[3] = to_tf32(v.w);
    }
    // cooperative load B = g_M (128 x 200) as tf32 bits
    for (int idx = tid; idx < FDIM * 50; idx += 256) {
        int k = idx / 50, c4 = idx % 50;
        float4 v = ((const float4*)g_M)[k * 50 + c4];
        unsigned* dst = &Bs[k * BS_STRIDE + c4 * 4];
        dst[0] = to_tf32(v.x); dst[1] = to_tf32(v.y);
        dst[2] = to_tf32(v.z); dst[3] = to_tf32(v.w);
    }
    __syncthreads();

    int lane = tid & 31, w = tid >> 5;
    int mw = w & 3, nw = w >> 2;
    int rbase = mw * 32;
    int nbase = nw * 96;
    int lr = lane >> 2, lc = lane & 3;

    float c[2][13][4];
    #pragma unroll
    for (int ms = 0; ms < 2; ms++)
        #pragma unroll
        for (int t = 0; t < 13; t++)
            #pragma unroll
            for (int u = 0; u < 4; u++) c[ms][t][u] = 0.0f;

    #pragma unroll
    for (int ks = 0; ks < 16; ks++) {
        int k0 = ks * 8;
        unsigned a[2][4];
        #pragma unroll
        for (int ms = 0; ms < 2; ms++) {
            int r0 = rbase + ms * 16 + lr;
            a[ms][0] = As[r0 * AS_STRIDE + k0 + lc];
            a[ms][1] = As[(r0 + 8) * AS_STRIDE + k0 + lc];
            a[ms][2] = As[r0 * AS_STRIDE + k0 + lc + 4];
            a[ms][3] = As[(r0 + 8) * AS_STRIDE + k0 + lc + 4];
        }
        #pragma unroll
        for (int t = 0; t < 13; t++) {
            int ncol = nbase + t * 8 + lr;
            unsigned b0 = Bs[(k0 + lc) * BS_STRIDE + ncol];
            unsigned b1 = Bs[(k0 + lc + 4) * BS_STRIDE + ncol];
            mma_tf32(c[0][t], a[0], b0, b1);
            mma_tf32(c[1][t], a[1], b0, b1);
        }
    }

    __syncthreads();
    float* Cs = (float*)Bs;
    #pragma unroll
    for (int ms = 0; ms < 2; ms++) {
        #pragma unroll
        for (int t = 0; t < 13; t++) {
            int rr = rbase + ms * 16 + lr;
            int cc = nbase + t * 8 + lc * 2;
            *(float2*)&Cs[rr * BS_STRIDE + cc] =
                make_float2(c[ms][t][0], c[ms][t][1]);
            *(float2*)&Cs[(rr + 8) * BS_STRIDE + cc] =
                make_float2(c[ms][t][2], c[ms][t][3]);
        }
    }
    __syncthreads();

    int r = tid >> 1, half = tid & 1;
    int nn = n0 + r;
    const float* Cr = &Cs[r * BS_STRIDE];
    float sum = 0.0f;
    #pragma unroll 2
    for (int jj = 0; jj < 50; jj++) {
        int j = half * 50 + jj;
        float zr = Cr[j] + sbias[j];
        float hr = Cr[HID + j] + sbias[HID + j];
        float omz = 0.5f * (1.0f - tanhfast(0.5f * zr));   // 1 - sigmoid(zr)
        float v = fmaxf(omz * tanhfast(hr), 0.0f);
        sum = fmaf(v, swout[j], sum);
    }
    sum += __shfl_down_sync(0xffffffffu, sum, 1);
    if (half == 0 && nn < n) out[nn] = sum + sbout;
}

// ---------------- launch ----------------------------------------------------
extern "C" void kernel_launch(void* const* d_in, const int* in_sizes, int n_in,
                              void* d_out, int out_size) {
    const float* x    = (const float*)d_in[0];
    const int*   ei   = (const int*)d_in[1];     // int32 (JAX canonicalizes)
    const float* ew   = (const float*)d_in[2];
    const float* Wcz  = (const float*)d_in[3];
    const float* bcz  = (const float*)d_in[4];
    const float* Wch  = (const float*)d_in[7];
    const float* bch  = (const float*)d_in[8];
    const float* Wlz  = (const float*)d_in[9];
    const float* blz  = (const float*)d_in[10];
    const float* Wlh  = (const float*)d_in[13];
    const float* blh  = (const float*)d_in[14];
    const float* Wout = (const float*)d_in[15];
    const float* bout = (const float*)d_in[16];
    float*       out  = (float*)d_out;

    int n = in_sizes[0] / FDIM;    // 100000
    int e = in_sizes[2];           // 1600000
    int nb = (n + SCAN_BLK - 1) / SCAN_BLK;

    static bool attr_set = false;
    if (!attr_set) {
        cudaFuncSetAttribute(k_tgemm,
                             cudaFuncAttributeMaxDynamicSharedMemorySize,
                             SMEM_BYTES);
        attr_set = true;
    }

    k_init<<<(n + 255) / 256, 256>>>(n);
    k_prep<<<(n * 32 + 255) / 256, 256>>>(x, n);
    k_fuseW<<<(FDIM * NC + 255) / 256, 256>>>(Wcz, Wch, Wlz, Wlh);
    k_fuseB<<<1, NC>>>(bcz, bch, Wlz, Wlh, blz, blh);
    k_deg_acc<<<(e + 255) / 256, 256>>>(ei, ew, e);
    k_dinv<<<(n + 255) / 256, 256>>>(n);
    k_scan1<<<nb, SCAN_BLK>>>(n);
    k_scan2<<<1, 128>>>(nb);
    k_scan3<<<(n + 255) / 256, 256>>>(n, e);
    k_fill<<<(e + 255) / 256, 256>>>(ei, ew, e);
    k_gather<<<(n * 32 + 255) / 256, 256>>>(n);
    k_tgemm<<<(n + 127) / 128, 256, SMEM_BYTES>>>(Wout, bout, out, n);
}

// round 7
// speedup vs baseline: 2.7359x; 1.0858x over previous
#include <cuda_runtime.h>
#include <cuda_fp16.h>
#include <cstdint>
#include <math.h>

#define MAXN 100000
#define MAXE 1600000
#define FDIM 128
#define HID  100
#define NC   200                 // 2*HID fused output columns: [z | h]
#define SCAN_BLK 1024
#define NB ((MAXN + SCAN_BLK - 1) / SCAN_BLK)

// tensor-gemm smem geometry
#define AS_STRIDE 132            // 128 k + 4 pad
#define BS_STRIDE 204            // 200 n + 4 pad
#define SMEM_BYTES ((128 * AS_STRIDE + FDIM * BS_STRIDE) * 4)   // 172,032

#define FIXSCALE 16777216.0f     // 2^24 fixed-point for edge-weight sums
#define FIXMASK ((1ull << 40) - 1)

// ---------------- scratch (static device memory; no runtime allocation) ----
__device__ unsigned long long g_pack[MAXN];   // (cnt<<40) | fix24(sum_w)
__device__ __align__(16) float g_dinv[MAXN];
__device__ int   g_off[MAXN + 1];
__device__ int   g_cur[MAXN];
__device__ int   g_bsum[NB];
__device__ __align__(16) unsigned long long g_edge[MAXE];    // packed (src, sw)
__device__ __align__(16) uint2 g_xh[(size_t)MAXN * 32];      // x as fp16
__device__ __align__(16) uint2 g_agg16[(size_t)MAXN * 32];   // aggx as fp16
__device__ __align__(16) float g_M[FDIM * NC];               // fused weights
__device__ __align__(16) float g_bias[NC];                   // fused biases

__device__ __forceinline__ float tanhfast(float x) {
    float y;
    asm("tanh.approx.f32 %0, %1;" : "=f"(y) : "f"(x));
    return y;
}
__device__ __forceinline__ unsigned to_tf32(float x) {
    unsigned u;
    asm("cvt.rna.tf32.f32 %0, %1;" : "=r"(u) : "f"(x));
    return u;
}
__device__ __forceinline__ void mma_tf32(float* c, const unsigned* a,
                                         unsigned b0, unsigned b1) {
    asm volatile(
        "mma.sync.aligned.m16n8k8.row.col.f32.tf32.tf32.f32 "
        "{%0,%1,%2,%3},{%4,%5,%6,%7},{%8,%9},{%0,%1,%2,%3};"
        : "+f"(c[0]), "+f"(c[1]), "+f"(c[2]), "+f"(c[3])
        : "r"(a[0]), "r"(a[1]), "r"(a[2]), "r"(a[3]), "r"(b0), "r"(b1));
}
__device__ __forceinline__ float4 h4_to_f4(uint2 u) {
    float2 fa = __half22float2(*(__half2*)&u.x);
    float2 fb = __half22float2(*(__half2*)&u.y);
    return make_float4(fa.x, fa.y, fb.x, fb.y);
}

// ---------------- init (pack=0) + x -> fp16, one kernel ---------------------
__global__ void k_init_prep(const float* __restrict__ x, int n) {
    int i = blockIdx.x * blockDim.x + threadIdx.x;
    if (i < n) g_pack[i] = 0ull;
    if (i >= n * 32) return;
    float4 v = ((const float4*)x)[i];
    uint2 u;
    *(__half2*)&u.x = __floats2half2_rn(v.x, v.y);
    *(__half2*)&u.y = __floats2half2_rn(v.z, v.w);
    g_xh[i] = u;
}

// ---------------- per-edge: one packed 64-bit atomic ------------------------
__global__ void k_deg_acc(const int* __restrict__ ei,
                          const float* __restrict__ ew, int e) {
    int i = blockIdx.x * blockDim.x + threadIdx.x;
    if (i < e) {
        int d = ei[(size_t)e + i];
        unsigned long long fix =
            (unsigned long long)__float2uint_rn(ew[i] * FIXSCALE);
        atomicAdd(&g_pack[d], (1ull << 40) | fix);
    }
}

// ---------------- scan1: decode pack -> dinv + block-local scan of cnt ------
__global__ void k_scan1(int n) {
    __shared__ int s[SCAN_BLK];
    int t = threadIdx.x;
    int idx = blockIdx.x * SCAN_BLK + t;
    int val = 0;
    if (idx < n) {
        unsigned long long p = g_pack[idx];
        val = (int)(p >> 40);
        float deg = 1.0f + (float)(p & FIXMASK) * (1.0f / FIXSCALE);
        g_dinv[idx] = rsqrtf(deg);     // deg >= 1 always (self loop)
    }
    s[t] = val;
    __syncthreads();
    #pragma unroll
    for (int off = 1; off < SCAN_BLK; off <<= 1) {
        int v = (t >= off) ? s[t - off] : 0;
        __syncthreads();
        s[t] += v;
        __syncthreads();
    }
    if (idx < n) g_off[idx] = s[t] - val;          // exclusive, block-local
    if (t == SCAN_BLK - 1) g_bsum[blockIdx.x] = s[t];
}

__global__ void k_scan2(int nb) {
    __shared__ int s[128];
    int t = threadIdx.x;
    int v = (t < nb) ? g_bsum[t] : 0;
    s[t] = v;
    __syncthreads();
    #pragma unroll
    for (int off = 1; off < 128; off <<= 1) {
        int u = (t >= off) ? s[t - off] : 0;
        __syncthreads();
        s[t] += u;
        __syncthreads();
    }
    if (t < nb) g_bsum[t] = s[t] - v;              // exclusive
}

__global__ void k_scan3(int n, int e) {
    int idx = blockIdx.x * blockDim.x + threadIdx.x;
    if (idx < n) {
        int v = g_off[idx] + g_bsum[idx >> 10];
        g_off[idx] = v;
        g_cur[idx] = v;
    }
    if (idx == 0) g_off[n] = e;
}

// ---------------- fill CSR: packed (src, dinv[s]*w) per slot ----------------
__global__ void k_fill(const int* __restrict__ ei,
                       const float* __restrict__ ew, int e) {
    int i = blockIdx.x * blockDim.x + threadIdx.x;
    if (i >= e) return;
    int s = ei[i];
    int d = ei[(size_t)e + i];
    float sw = g_dinv[s] * ew[i];
    int pos = atomicAdd(&g_cur[d], 1);
    g_edge[pos] = (unsigned long long)(unsigned)s |
                  ((unsigned long long)__float_as_uint(sw) << 32);
}

// ---------------- gather: one warp per node, fp16 payload, fp32 accum -------
// result = dinv[d] * ( dinv[d]*x[d] + sum sw*x[s] )
__global__ void k_gather(int n) {
    int w = (blockIdx.x * blockDim.x + threadIdx.x) >> 5;
    int lane = threadIdx.x & 31;
    if (w >= n) return;
    int beg = g_off[w];
    int end = g_off[w + 1];
    float dd = g_dinv[w];
    float4 acc = h4_to_f4(g_xh[(size_t)w * 32 + lane]);
    acc.x *= dd; acc.y *= dd; acc.z *= dd; acc.w *= dd;

    int j = beg;
    int m4 = beg + ((end - beg) & ~3);
    for (; j < m4; j += 4) {
        unsigned long long m0 = g_edge[j];
        unsigned long long m1 = g_edge[j + 1];
        unsigned long long m2 = g_edge[j + 2];
        unsigned long long m3 = g_edge[j + 3];
        float4 v0 = h4_to_f4(g_xh[(size_t)(unsigned)m0 * 32 + lane]);
        float4 v1 = h4_to_f4(g_xh[(size_t)(unsigned)m1 * 32 + lane]);
        float4 v2 = h4_to_f4(g_xh[(size_t)(unsigned)m2 * 32 + lane]);
        float4 v3 = h4_to_f4(g_xh[(size_t)(unsigned)m3 * 32 + lane]);
        float n0 = __uint_as_float((unsigned)(m0 >> 32));
        float n1 = __uint_as_float((unsigned)(m1 >> 32));
        float n2 = __uint_as_float((unsigned)(m2 >> 32));
        float n3 = __uint_as_float((unsigned)(m3 >> 32));
        acc.x = fmaf(v0.x, n0, acc.x); acc.y = fmaf(v0.y, n0, acc.y);
        acc.z = fmaf(v0.z, n0, acc.z); acc.w = fmaf(v0.w, n0, acc.w);
        acc.x = fmaf(v1.x, n1, acc.x); acc.y = fmaf(v1.y, n1, acc.y);
        acc.z = fmaf(v1.z, n1, acc.z); acc.w = fmaf(v1.w, n1, acc.w);
        acc.x = fmaf(v2.x, n2, acc.x); acc.y = fmaf(v2.y, n2, acc.y);
        acc.z = fmaf(v2.z, n2, acc.z); acc.w = fmaf(v2.w, n2, acc.w);
        acc.x = fmaf(v3.x, n3, acc.x); acc.y = fmaf(v3.y, n3, acc.y);
        acc.w = fmaf(v3.w, n3, acc.w); acc.z = fmaf(v3.z, n3, acc.z);
    }
    for (; j < end; j++) {
        unsigned long long m = g_edge[j];
        float nrm = __uint_as_float((unsigned)(m >> 32));
        float4 v = h4_to_f4(g_xh[(size_t)(unsigned)m * 32 + lane]);
        acc.x = fmaf(v.x, nrm, acc.x); acc.y = fmaf(v.y, nrm, acc.y);
        acc.z = fmaf(v.z, nrm, acc.z); acc.w = fmaf(v.w, nrm, acc.w);
    }
    uint2 u;
    *(__half2*)&u.x = __floats2half2_rn(acc.x * dd, acc.y * dd);
    *(__half2*)&u.y = __floats2half2_rn(acc.z * dd, acc.w * dd);
    g_agg16[(size_t)w * 32 + lane] = u;
}

// ---------------- fused weights+bias: one block per output column -----------
// block j: M[:,j] = A @ Wl[:,jj],  bias[j] = bl[jj] + dot(bc, Wl[:,jj])
__global__ void __launch_bounds__(128) k_fuse(
        const float* __restrict__ Wcz, const float* __restrict__ Wch,
        const float* __restrict__ bcz, const float* __restrict__ bch,
        const float* __restrict__ Wlz, const float* __restrict__ Wlh,
        const float* __restrict__ blz, const float* __restrict__ blh) {
    __shared__ float wl[HID];
    __shared__ float red[128];
    int j = blockIdx.x;                 // 0..199
    int t = threadIdx.x;                // 0..127
    int jj = (j < HID) ? j : j - HID;
    const float* A  = (j < HID) ? Wcz : Wch;
    const float* bc = (j < HID) ? bcz : bch;
    const float* Wl = (j < HID) ? Wlz : Wlh;
    const float* bl = (j < HID) ? blz : blh;

    float p = 0.0f;
    if (t < HID) {
        float v = Wl[t * HID + jj];
        wl[t] = v;
        p = bc[t] * v;
    }
    red[t] = p;
    __syncthreads();

    // M column: each thread one f-row
    const float* Ar = A + t * HID;
    float s = 0.0f;
    #pragma unroll 4
    for (int k = 0; k < HID; k++)
        s = fmaf(Ar[k], wl[k], s);
    g_M[t * NC + j] = s;

    // bias reduction
    #pragma unroll
    for (int off = 64; off > 0; off >>= 1) {
        if (t < off) red[t] += red[t + off];
        __syncthreads();
    }
    if (t == 0) g_bias[j] = bl[jj] + red[0];
}

// ---------------- tf32 tensor-core GEMM + fused TGCN epilogue ---------------
__global__ void __launch_bounds__(256, 1)
k_tgemm(const float* __restrict__ Wout, const float* __restrict__ bout,
        float* __restrict__ out, int n) {
    extern __shared__ unsigned smem[];
    unsigned* As = smem;                       // [128][AS_STRIDE]
    unsigned* Bs = smem + 128 * AS_STRIDE;     // [FDIM][BS_STRIDE], reused as C

    __shared__ float sbias[NC];
    __shared__ float swout[HID];
    __shared__ float sbout;

    int tid = threadIdx.x;
    int n0 = blockIdx.x * 128;

    if (tid < NC)  sbias[tid] = g_bias[tid];
    if (tid < HID) swout[tid] = Wout[tid];
    if (tid == 0)  sbout = bout[0];

    // cooperative load A tile (128 x 128) from fp16 aggx (fp16 -> tf32 exact)
    for (int idx = tid; idx < 128 * 32; idx += 256) {
        int r = idx >> 5, c4 = idx & 31;
        int nn = n0 + r;
        uint2 u = (nn < n) ? g_agg16[(size_t)nn * 32 + c4] : make_uint2(0u, 0u);
        float4 v = h4_to_f4(u);
        unsigned* dst = &As[r * AS_STRIDE + c4 * 4];
        dst[0] = to_tf32(v.x); dst[1] = to_tf32(v.y);
        dst[2] = to_tf32(v.z); dst[3] = to_tf32(v.w);
    }
    // cooperative load B = g_M (128 x 200) as tf32 bits
    for (int idx = tid; idx < FDIM * 50; idx += 256) {
        int k = idx / 50, c4 = idx % 50;
        float4 v = ((const float4*)g_M)[k * 50 + c4];
        unsigned* dst = &Bs[k * BS_STRIDE + c4 * 4];
        dst[0] = to_tf32(v.x); dst[1] = to_tf32(v.y);
        dst[2] = to_tf32(v.z); dst[3] = to_tf32(v.w);
    }
    __syncthreads();

    int lane = tid & 31, w = tid >> 5;
    int mw = w & 3, nw = w >> 2;
    int rbase = mw * 32;
    int nbase = nw * 96;
    int lr = lane >> 2, lc = lane & 3;

    float c[2][13][4];
    #pragma unroll
    for (int ms = 0; ms < 2; ms++)
        #pragma unroll
        for (int t = 0; t < 13; t++)
            #pragma unroll
            for (int u = 0; u < 4; u++) c[ms][t][u] = 0.0f;

    #pragma unroll
    for (int ks = 0; ks < 16; ks++) {
        int k0 = ks * 8;
        unsigned a[2][4];
        #pragma unroll
        for (int ms = 0; ms < 2; ms++) {
            int r0 = rbase + ms * 16 + lr;
            a[ms][0] = As[r0 * AS_STRIDE + k0 + lc];
            a[ms][1] = As[(r0 + 8) * AS_STRIDE + k0 + lc];
            a[ms][2] = As[r0 * AS_STRIDE + k0 + lc + 4];
            a[ms][3] = As[(r0 + 8) * AS_STRIDE + k0 + lc + 4];
        }
        #pragma unroll
        for (int t = 0; t < 13; t++) {
            int ncol = nbase + t * 8 + lr;
            unsigned b0 = Bs[(k0 + lc) * BS_STRIDE + ncol];
            unsigned b1 = Bs[(k0 + lc + 4) * BS_STRIDE + ncol];
            mma_tf32(c[0][t], a[0], b0, b1);
            mma_tf32(c[1][t], a[1], b0, b1);
        }
    }

    __syncthreads();
    float* Cs = (float*)Bs;
    #pragma unroll
    for (int ms = 0; ms < 2; ms++) {
        #pragma unroll
        for (int t = 0; t < 13; t++) {
            int rr = rbase + ms * 16 + lr;
            int cc = nbase + t * 8 + lc * 2;
            *(float2*)&Cs[rr * BS_STRIDE + cc] =
                make_float2(c[ms][t][0], c[ms][t][1]);
            *(float2*)&Cs[(rr + 8) * BS_STRIDE + cc] =
                make_float2(c[ms][t][2], c[ms][t][3]);
        }
    }
    __syncthreads();

    int r = tid >> 1, half = tid & 1;
    int nn = n0 + r;
    const float* Cr = &Cs[r * BS_STRIDE];
    float sum = 0.0f;
    #pragma unroll 2
    for (int jj = 0; jj < 50; jj++) {
        int j = half * 50 + jj;
        float zr = Cr[j] + sbias[j];
        float hr = Cr[HID + j] + sbias[HID + j];
        float omz = 0.5f * (1.0f - tanhfast(0.5f * zr));   // 1 - sigmoid(zr)
        float v = fmaxf(omz * tanhfast(hr), 0.0f);
        sum = fmaf(v, swout[j], sum);
    }
    sum += __shfl_down_sync(0xffffffffu, sum, 1);
    if (half == 0 && nn < n) out[nn] = sum + sbout;
}

// ---------------- launch ----------------------------------------------------
extern "C" void kernel_launch(void* const* d_in, const int* in_sizes, int n_in,
                              void* d_out, int out_size) {
    const float* x    = (const float*)d_in[0];
    const int*   ei   = (const int*)d_in[1];     // int32 (JAX canonicalizes)
    const float* ew   = (const float*)d_in[2];
    const float* Wcz  = (const float*)d_in[3];
    const float* bcz  = (const float*)d_in[4];
    const float* Wch  = (const float*)d_in[7];
    const float* bch  = (const float*)d_in[8];
    const float* Wlz  = (const float*)d_in[9];
    const float* blz  = (const float*)d_in[10];
    const float* Wlh  = (const float*)d_in[13];
    const float* blh  = (const float*)d_in[14];
    const float* Wout = (const float*)d_in[15];
    const float* bout = (const float*)d_in[16];
    float*       out  = (float*)d_out;

    int n = in_sizes[0] / FDIM;    // 100000
    int e = in_sizes[2];           // 1600000
    int nb = (n + SCAN_BLK - 1) / SCAN_BLK;

    static bool attr_set = false;
    if (!attr_set) {
        cudaFuncSetAttribute(k_tgemm,
                             cudaFuncAttributeMaxDynamicSharedMemorySize,
                             SMEM_BYTES);
        attr_set = true;
    }

    k_init_prep<<<(n * 32 + 255) / 256, 256>>>(x, n);
    k_fuse<<<NC, 128>>>(Wcz, Wch, bcz, bch, Wlz, Wlh, blz, blh);
    k_deg_acc<<<(e + 255) / 256, 256>>>(ei, ew, e);
    k_scan1<<<nb, SCAN_BLK>>>(n);
    k_scan2<<<1, 128>>>(nb);
    k_scan3<<<(n + 255) / 256, 256>>>(n, e);
    k_fill<<<(e + 255) / 256, 256>>>(ei, ew, e);
    k_gather<<<(n * 32 + 255) / 256, 256>>>(n);
    k_tgemm<<<(n + 127) / 128, 256, SMEM_BYTES>>>(Wout, bout, out, n);
}

// round 8
// speedup vs baseline: 3.1406x; 1.1479x over previous
#include <cuda_runtime.h>
#include <cuda_fp16.h>
#include <cstdint>
#include <math.h>

#define MAXN 100000
#define MAXE 1600000
#define FDIM 128
#define HID  100
#define NC   200                 // 2*HID fused output columns: [z | h]
#define SCAN_BLK 1024
#define NB ((MAXN + SCAN_BLK - 1) / SCAN_BLK)

// fp16 tensor-gemm smem geometry (halves)
#define AS_H 136                 // 128 k + 8 pad  (272 B row ≡ 16 mod 128 -> conflict-free ldmatrix)
#define BS_H 200                 // 400 B row ≡ 16 mod 128 -> conflict-free
#define CS_STRIDE 204            // f32 C stride
#define AS_BYTES (128 * AS_H * 2)          // 34,816
#define BS_BYTES (FDIM * BS_H * 2)         // 51,200
#define SMEM_BYTES (128 * CS_STRIDE * 4)   // 104,448  (C overlay dominates)

#define FIXSCALE 16777216.0f     // 2^24 fixed-point for edge-weight sums
#define FIXMASK ((1ull << 40) - 1)

// ---------------- scratch (static device memory; no runtime allocation) ----
__device__ unsigned long long g_pack[MAXN];   // (cnt<<40) | fix24(sum_w)
__device__ __align__(16) float g_dinv[MAXN];
__device__ int   g_off[MAXN + 1];
__device__ int   g_cur[MAXN];
__device__ int   g_bsum[NB];
__device__ __align__(16) unsigned long long g_edge[MAXE];    // packed (src, sw)
__device__ __align__(16) uint2 g_xh[(size_t)MAXN * 32];      // x as fp16
__device__ __align__(16) uint2 g_agg16[(size_t)MAXN * 32];   // aggx as fp16
__device__ __align__(16) __half g_Mh[FDIM * NC];             // fused weights fp16
__device__ __align__(16) float g_bias[NC];                   // fused biases

__device__ __forceinline__ float tanhfast(float x) {
    float y;
    asm("tanh.approx.f32 %0, %1;" : "=f"(y) : "f"(x));
    return y;
}
__device__ __forceinline__ void ldmatrix_x4(unsigned& r0, unsigned& r1,
                                            unsigned& r2, unsigned& r3,
                                            unsigned addr) {
    asm volatile("ldmatrix.sync.aligned.m8n8.x4.shared.b16 {%0,%1,%2,%3}, [%4];"
                 : "=r"(r0), "=r"(r1), "=r"(r2), "=r"(r3) : "r"(addr));
}
__device__ __forceinline__ void ldmatrix_x2_trans(unsigned& r0, unsigned& r1,
                                                  unsigned addr) {
    asm volatile("ldmatrix.sync.aligned.m8n8.x2.trans.shared.b16 {%0,%1}, [%2];"
                 : "=r"(r0), "=r"(r1) : "r"(addr));
}
__device__ __forceinline__ void mma_f16(float* c, const unsigned* a,
                                        unsigned b0, unsigned b1) {
    asm volatile(
        "mma.sync.aligned.m16n8k16.row.col.f32.f16.f16.f32 "
        "{%0,%1,%2,%3},{%4,%5,%6,%7},{%8,%9},{%0,%1,%2,%3};"
        : "+f"(c[0]), "+f"(c[1]), "+f"(c[2]), "+f"(c[3])
        : "r"(a[0]), "r"(a[1]), "r"(a[2]), "r"(a[3]), "r"(b0), "r"(b1));
}
__device__ __forceinline__ float4 h4_to_f4(uint2 u) {
    float2 fa = __half22float2(*(__half2*)&u.x);
    float2 fb = __half22float2(*(__half2*)&u.y);
    return make_float4(fa.x, fa.y, fb.x, fb.y);
}

// ---------------- init (pack=0) + x -> fp16, one kernel ---------------------
__global__ void k_init_prep(const float* __restrict__ x, int n) {
    int i = blockIdx.x * blockDim.x + threadIdx.x;
    if (i < n) g_pack[i] = 0ull;
    if (i >= n * 32) return;
    float4 v = ((const float4*)x)[i];
    uint2 u;
    *(__half2*)&u.x = __floats2half2_rn(v.x, v.y);
    *(__half2*)&u.y = __floats2half2_rn(v.z, v.w);
    g_xh[i] = u;
}

// ---------------- per-edge: one packed 64-bit atomic ------------------------
__global__ void k_deg_acc(const int* __restrict__ ei,
                          const float* __restrict__ ew, int e) {
    int i = blockIdx.x * blockDim.x + threadIdx.x;
    if (i < e) {
        int d = ei[(size_t)e + i];
        unsigned long long fix =
            (unsigned long long)__float2uint_rn(ew[i] * FIXSCALE);
        atomicAdd(&g_pack[d], (1ull << 40) | fix);
    }
}

// ---------------- scan1: decode pack -> dinv + block-local scan of cnt ------
__global__ void k_scan1(int n) {
    __shared__ int s[SCAN_BLK];
    int t = threadIdx.x;
    int idx = blockIdx.x * SCAN_BLK + t;
    int val = 0;
    if (idx < n) {
        unsigned long long p = g_pack[idx];
        val = (int)(p >> 40);
        float deg = 1.0f + (float)(p & FIXMASK) * (1.0f / FIXSCALE);
        g_dinv[idx] = rsqrtf(deg);
    }
    s[t] = val;
    __syncthreads();
    #pragma unroll
    for (int off = 1; off < SCAN_BLK; off <<= 1) {
        int v = (t >= off) ? s[t - off] : 0;
        __syncthreads();
        s[t] += v;
        __syncthreads();
    }
    if (idx < n) g_off[idx] = s[t] - val;
    if (t == SCAN_BLK - 1) g_bsum[blockIdx.x] = s[t];
}

__global__ void k_scan2(int nb) {
    __shared__ int s[128];
    int t = threadIdx.x;
    int v = (t < nb) ? g_bsum[t] : 0;
    s[t] = v;
    __syncthreads();
    #pragma unroll
    for (int off = 1; off < 128; off <<= 1) {
        int u = (t >= off) ? s[t - off] : 0;
        __syncthreads();
        s[t] += u;
        __syncthreads();
    }
    if (t < nb) g_bsum[t] = s[t] - v;
}

__global__ void k_scan3(int n, int e) {
    int idx = blockIdx.x * blockDim.x + threadIdx.x;
    if (idx < n) {
        int v = g_off[idx] + g_bsum[idx >> 10];
        g_off[idx] = v;
        g_cur[idx] = v;
    }
    if (idx == 0) g_off[n] = e;
}

// ---------------- fill CSR: packed (src, dinv[s]*w) per slot ----------------
__global__ void k_fill(const int* __restrict__ ei,
                       const float* __restrict__ ew, int e) {
    int i = blockIdx.x * blockDim.x + threadIdx.x;
    if (i >= e) return;
    int s = ei[i];
    int d = ei[(size_t)e + i];
    float sw = g_dinv[s] * ew[i];
    int pos = atomicAdd(&g_cur[d], 1);
    g_edge[pos] = (unsigned long long)(unsigned)s |
                  ((unsigned long long)__float_as_uint(sw) << 32);
}

// ---------------- gather: one warp per node, fp16 payload, fp32 accum -------
__global__ void k_gather(int n) {
    int w = (blockIdx.x * blockDim.x + threadIdx.x) >> 5;
    int lane = threadIdx.x & 31;
    if (w >= n) return;
    int beg = g_off[w];
    int end = g_off[w + 1];
    float dd = g_dinv[w];
    float4 acc = h4_to_f4(g_xh[(size_t)w * 32 + lane]);
    acc.x *= dd; acc.y *= dd; acc.z *= dd; acc.w *= dd;

    int j = beg;
    int m4 = beg + ((end - beg) & ~3);
    for (; j < m4; j += 4) {
        unsigned long long m0 = g_edge[j];
        unsigned long long m1 = g_edge[j + 1];
        unsigned long long m2 = g_edge[j + 2];
        unsigned long long m3 = g_edge[j + 3];
        float4 v0 = h4_to_f4(g_xh[(size_t)(unsigned)m0 * 32 + lane]);
        float4 v1 = h4_to_f4(g_xh[(size_t)(unsigned)m1 * 32 + lane]);
        float4 v2 = h4_to_f4(g_xh[(size_t)(unsigned)m2 * 32 + lane]);
        float4 v3 = h4_to_f4(g_xh[(size_t)(unsigned)m3 * 32 + lane]);
        float n0 = __uint_as_float((unsigned)(m0 >> 32));
        float n1 = __uint_as_float((unsigned)(m1 >> 32));
        float n2 = __uint_as_float((unsigned)(m2 >> 32));
        float n3 = __uint_as_float((unsigned)(m3 >> 32));
        acc.x = fmaf(v0.x, n0, acc.x); acc.y = fmaf(v0.y, n0, acc.y);
        acc.z = fmaf(v0.z, n0, acc.z); acc.w = fmaf(v0.w, n0, acc.w);
        acc.x = fmaf(v1.x, n1, acc.x); acc.y = fmaf(v1.y, n1, acc.y);
        acc.z = fmaf(v1.z, n1, acc.z); acc.w = fmaf(v1.w, n1, acc.w);
        acc.x = fmaf(v2.x, n2, acc.x); acc.y = fmaf(v2.y, n2, acc.y);
        acc.z = fmaf(v2.z, n2, acc.z); acc.w = fmaf(v2.w, n2, acc.w);
        acc.x = fmaf(v3.x, n3, acc.x); acc.y = fmaf(v3.y, n3, acc.y);
        acc.z = fmaf(v3.z, n3, acc.z); acc.w = fmaf(v3.w, n3, acc.w);
    }
    for (; j < end; j++) {
        unsigned long long m = g_edge[j];
        float nrm = __uint_as_float((unsigned)(m >> 32));
        float4 v = h4_to_f4(g_xh[(size_t)(unsigned)m * 32 + lane]);
        acc.x = fmaf(v.x, nrm, acc.x); acc.y = fmaf(v.y, nrm, acc.y);
        acc.z = fmaf(v.z, nrm, acc.z); acc.w = fmaf(v.w, nrm, acc.w);
    }
    uint2 u;
    *(__half2*)&u.x = __floats2half2_rn(acc.x * dd, acc.y * dd);
    *(__half2*)&u.y = __floats2half2_rn(acc.z * dd, acc.w * dd);
    g_agg16[(size_t)w * 32 + lane] = u;
}

// ---------------- fused weights+bias: one block per output column -----------
__global__ void __launch_bounds__(128) k_fuse(
        const float* __restrict__ Wcz, const float* __restrict__ Wch,
        const float* __restrict__ bcz, const float* __restrict__ bch,
        const float* __restrict__ Wlz, const float* __restrict__ Wlh,
        const float* __restrict__ blz, const float* __restrict__ blh) {
    __shared__ float wl[HID];
    __shared__ float red[128];
    int j = blockIdx.x;                 // 0..199
    int t = threadIdx.x;                // 0..127
    int jj = (j < HID) ? j : j - HID;
    const float* A  = (j < HID) ? Wcz : Wch;
    const float* bc = (j < HID) ? bcz : bch;
    const float* Wl = (j < HID) ? Wlz : Wlh;
    const float* bl = (j < HID) ? blz : blh;

    float p = 0.0f;
    if (t < HID) {
        float v = Wl[t * HID + jj];
        wl[t] = v;
        p = bc[t] * v;
    }
    red[t] = p;
    __syncthreads();

    const float* Ar = A + t * HID;
    float s = 0.0f;
    #pragma unroll 4
    for (int k = 0; k < HID; k++)
        s = fmaf(Ar[k], wl[k], s);
    g_Mh[t * NC + j] = __float2half_rn(s);

    #pragma unroll
    for (int off = 64; off > 0; off >>= 1) {
        if (t < off) red[t] += red[t + off];
        __syncthreads();
    }
    if (t == 0) g_bias[j] = bl[jj] + red[0];
}

// ---------------- fp16 tensor-core GEMM + fused TGCN epilogue ---------------
// block: 128 rows x 200 cols, K=128, fp16 MMA m16n8k16 with ldmatrix.
__global__ void __launch_bounds__(256, 1)
k_tgemm(const float* __restrict__ Wout, const float* __restrict__ bout,
        float* __restrict__ out, int n) {
    extern __shared__ __align__(16) char smem[];
    __half* As = (__half*)smem;                        // [128][AS_H]
    __half* Bs = (__half*)(smem + AS_BYTES);           // [FDIM][BS_H]

    __shared__ float sbias[NC];
    __shared__ float swout[HID];
    __shared__ float sbout;

    int tid = threadIdx.x;
    int n0 = blockIdx.x * 128;

    if (tid < NC)  sbias[tid] = g_bias[tid];
    if (tid < HID) swout[tid] = Wout[tid];
    if (tid == 0)  sbout = bout[0];

    // cooperative load A tile (128 x 128 fp16) straight from g_agg16
    for (int idx = tid; idx < 128 * 32; idx += 256) {
        int r = idx >> 5, c4 = idx & 31;
        int nn = n0 + r;
        uint2 u = (nn < n) ? g_agg16[(size_t)nn * 32 + c4] : make_uint2(0u, 0u);
        *(uint2*)&As[r * AS_H + c4 * 4] = u;
    }
    // cooperative load B = g_Mh (128 x 200 fp16)
    for (int idx = tid; idx < FDIM * 50; idx += 256) {
        int k = idx / 50, c = idx % 50;
        *(uint2*)&Bs[k * BS_H + c * 4] = ((const uint2*)g_Mh)[k * 50 + c];
    }
    __syncthreads();

    int lane = tid & 31, w = tid >> 5;
    int mw = w & 3, nw = w >> 2;
    int rbase = mw * 32;
    int nbase = nw * 96;
    int lr = lane >> 2, lc = lane & 3;

    unsigned as_base = (unsigned)__cvta_generic_to_shared(As);
    unsigned bs_base = (unsigned)__cvta_generic_to_shared(Bs);

    // ldmatrix lane address components
    int a_idx = lane & 7, a_grp = lane >> 3;            // x4: 4 groups of 8
    int b_row_lane = lane & 15;                          // x2: lanes 0-15

    float c[2][13][4];
    #pragma unroll
    for (int ms = 0; ms < 2; ms++)
        #pragma unroll
        for (int t = 0; t < 13; t++)
            #pragma unroll
            for (int u = 0; u < 4; u++) c[ms][t][u] = 0.0f;

    #pragma unroll
    for (int ks = 0; ks < 8; ks++) {
        int k0 = ks * 16;
        unsigned a[2][4];
        #pragma unroll
        for (int ms = 0; ms < 2; ms++) {
            int row = rbase + ms * 16 + (a_grp & 1) * 8 + a_idx;
            int col = k0 + (a_grp >> 1) * 8;
            unsigned addr = as_base + (row * AS_H + col) * 2;
            ldmatrix_x4(a[ms][0], a[ms][1], a[ms][2], a[ms][3], addr);
        }
        #pragma unroll
        for (int t = 0; t < 13; t++) {
            int ncol = nbase + t * 8;
            unsigned baddr = bs_base + ((k0 + b_row_lane) * BS_H + ncol) * 2;
            unsigned b0, b1;
            ldmatrix_x2_trans(b0, b1, baddr);
            mma_f16(c[0][t], a[0], b0, b1);
            mma_f16(c[1][t], a[1], b0, b1);
        }
    }

    __syncthreads();
    float* Cs = (float*)smem;                           // overlay
    #pragma unroll
    for (int ms = 0; ms < 2; ms++) {
        #pragma unroll
        for (int t = 0; t < 13; t++) {
            int rr = rbase + ms * 16 + lr;
            int cc = nbase + t * 8 + lc * 2;
            *(float2*)&Cs[rr * CS_STRIDE + cc] =
                make_float2(c[ms][t][0], c[ms][t][1]);
            *(float2*)&Cs[(rr + 8) * CS_STRIDE + cc] =
                make_float2(c[ms][t][2], c[ms][t][3]);
        }
    }
    __syncthreads();

    int r = tid >> 1, half = tid & 1;
    int nn = n0 + r;
    const float* Cr = &Cs[r * CS_STRIDE];
    float sum = 0.0f;
    #pragma unroll 2
    for (int jj = 0; jj < 50; jj++) {
        int j = half * 50 + jj;
        float zr = Cr[j] + sbias[j];
        float hr = Cr[HID + j] + sbias[HID + j];
        float omz = 0.5f * (1.0f - tanhfast(0.5f * zr));   // 1 - sigmoid(zr)
        float v = fmaxf(omz * tanhfast(hr), 0.0f);
        sum = fmaf(v, swout[j], sum);
    }
    sum += __shfl_down_sync(0xffffffffu, sum, 1);
    if (half == 0 && nn < n) out[nn] = sum + sbout;
}

// ---------------- launch ----------------------------------------------------
extern "C" void kernel_launch(void* const* d_in, const int* in_sizes, int n_in,
                              void* d_out, int out_size) {
    const float* x    = (const float*)d_in[0];
    const int*   ei   = (const int*)d_in[1];     // int32 (JAX canonicalizes)
    const float* ew   = (const float*)d_in[2];
    const float* Wcz  = (const float*)d_in[3];
    const float* bcz  = (const float*)d_in[4];
    const float* Wch  = (const float*)d_in[7];
    const float* bch  = (const float*)d_in[8];
    const float* Wlz  = (const float*)d_in[9];
    const float* blz  = (const float*)d_in[10];
    const float* Wlh  = (const float*)d_in[13];
    const float* blh  = (const float*)d_in[14];
    const float* Wout = (const float*)d_in[15];
    const float* bout = (const float*)d_in[16];
    float*       out  = (float*)d_out;

    int n = in_sizes[0] / FDIM;    // 100000
    int e = in_sizes[2];           // 1600000
    int nb = (n + SCAN_BLK - 1) / SCAN_BLK;

    static bool attr_set = false;
    if (!attr_set) {
        cudaFuncSetAttribute(k_tgemm,
                             cudaFuncAttributeMaxDynamicSharedMemorySize,
                             SMEM_BYTES);
        attr_set = true;
    }

    k_init_prep<<<(n * 32 + 255) / 256, 256>>>(x, n);
    k_fuse<<<NC, 128>>>(Wcz, Wch, bcz, bch, Wlz, Wlh, blz, blh);
    k_deg_acc<<<(e + 255) / 256, 256>>>(ei, ew, e);
    k_scan1<<<nb, SCAN_BLK>>>(n);
    k_scan2<<<1, 128>>>(nb);
    k_scan3<<<(n + 255) / 256, 256>>>(n, e);
    k_fill<<<(e + 255) / 256, 256>>>(ei, ew, e);
    k_gather<<<(n * 32 + 255) / 256, 256>>>(n);
    k_tgemm<<<(n + 127) / 128, 256, SMEM_BYTES>>>(Wout, bout, out, n);
}